// round 6
// baseline (speedup 1.0000x reference)
#include <cuda_runtime.h>
#include <math.h>

#define NN    8192
#define EE    262144
#define CC    64
#define ELLW  128   // Poisson(32) tail beyond 128 ~ 1e-40

// ---- scratch (__device__ globals; zeroed at module load) ----
__device__ int    g_cnt[NN];           // raw scatter counts (self-reset by dedup)
__device__ int    g_cnt2[NN];          // deduped counts
__device__ float  g_deg[NN];
__device__ float  g_sinv[NN];          // rsqrt(deg)
__device__ int2   g_ellcj[NN * ELLW];  // raw: (col, edge id)
__device__ float2 g_ell[NN * ELLW];    // winners: (col_as_float, w -> coef)
__device__ float  g_T1[NN * CC];
__device__ float  g_gate;
__device__ int    g_is32;

__device__ __forceinline__ void load_rc(const void* ei, int j, int& r, int& c) {
    if (g_is32) {
        const int* e = (const int*)ei;
        r = e[j]; c = e[EE + j];
    } else {
        const long long* e = (const long long*)ei;
        r = (int)e[j]; c = (int)e[EE + j];
    }
}

// 0) dtype detect + gate (one warp)
__global__ void k_setup(const void* ei, const float* __restrict__ aw) {
    const long long* e64 = (const long long*)ei;
    int lane = threadIdx.x;
    long long v0 = e64[lane];
    long long v1 = e64[32 + lane];
    int bad = (v0 < 0 || v0 >= NN || v1 < 0 || v1 >= NN);
    unsigned any = __any_sync(0xffffffffu, bad);
    if (lane == 0) {
        g_is32 = any ? 1 : 0;
        g_gate = 1.0f / (1.0f + expf(-aw[0]));
    }
}

// 1) scatter edges into per-row lists (order nondeterministic; j recorded)
__global__ void k_scatter(const void* __restrict__ ei) {
    int j = blockIdx.x * blockDim.x + threadIdx.x;
    if (j >= EE) return;
    int r, c; load_rc(ei, j, r, c);
    int pos = atomicAdd(&g_cnt[r], 1);
    if (pos < ELLW) g_ellcj[r * ELLW + pos] = make_int2(c, j);
}

// 2) per-row dedupe via 256-slot per-warp shared hash.
//    entry = (col+1)<<18 | j  -> atomicMax = last-write-wins on edge id.
//    Self-resets g_cnt[r] for the next graph replay.
__global__ void k_dedup(const float* __restrict__ ew) {
    __shared__ unsigned tab[8][256];
    int wid  = threadIdx.x >> 5;
    int lane = threadIdx.x & 31;
    #pragma unroll
    for (int i = 0; i < 8; i++) tab[wid][lane + 32 * i] = 0u;
    __syncwarp();

    int r = blockIdx.x * 8 + wid;
    int nnz = min(g_cnt[r], ELLW);

    for (int k = lane; k < nnz; k += 32) {
        int2 cj = g_ellcj[r * ELLW + k];
        unsigned c = (unsigned)cj.x;
        unsigned entry = ((c + 1u) << 18) | (unsigned)cj.y;
        unsigned h = (c * 2654435761u) >> 24;
        for (;;) {
            unsigned cur = tab[wid][h];
            if (cur == 0u) {
                unsigned old = atomicCAS(&tab[wid][h], 0u, entry);
                if (old == 0u) break;
                cur = old;
            }
            if ((cur >> 18) == c + 1u) { atomicMax(&tab[wid][h], entry); break; }
            h = (h + 1u) & 255u;
        }
    }
    __syncwarp();

    float gate = g_gate;
    float degsum = 0.0f;
    int outpos = 0;
    #pragma unroll
    for (int it = 0; it < 8; it++) {
        unsigned e = tab[wid][lane + 32 * it];
        bool alive = (e != 0u);
        int c = 0; float wv = 0.0f;
        if (alive) {
            c = (int)(e >> 18) - 1;
            int j = (int)(e & 0x3FFFFu);
            wv = __ldg(&ew[j]) * gate;
            degsum += wv;
        }
        unsigned bal = __ballot_sync(0xffffffffu, alive);
        int pos = outpos + __popc(bal & ((1u << lane) - 1u));
        if (alive) g_ell[r * ELLW + pos] = make_float2(__int_as_float(c), wv);
        outpos += __popc(bal);
    }
    #pragma unroll
    for (int off = 16; off > 0; off >>= 1)
        degsum += __shfl_xor_sync(0xffffffffu, degsum, off);
    if (lane == 0) {
        float d = 1.0f + degsum;
        g_cnt2[r] = outpos;
        g_deg[r]  = d;
        g_sinv[r] = rsqrtf(d);
        g_cnt[r]  = 0;              // reset for next replay
    }
}

// 3) T1 = L x ; finalizes coefficients in-place (g_ell[].y -> -sr*w*sc)
__global__ void k_spmm1(const float* __restrict__ x) {
    int gtid = blockIdx.x * blockDim.x + threadIdx.x;
    int r = gtid >> 5;
    int lane = gtid & 31;

    const float2* __restrict__ x2 = (const float2*)x;
    float dr = g_deg[r];
    float sr = g_sinv[r];
    float diag = 1.0f - 1.0f / dr;

    float2 acc = __ldg(&x2[r * 32 + lane]);
    acc.x *= diag; acc.y *= diag;

    int nnz = g_cnt2[r];
    float2* __restrict__ ell = g_ell + r * ELLW;
    #pragma unroll 8
    for (int k = 0; k < nnz; k++) {
        float2 e = ell[k];
        int c = __float_as_int(e.x);
        float coef = -sr * e.y * __ldg(&g_sinv[c]);
        if (lane == 0) ell[k].y = coef;          // final coef for fused pass
        float2 zc = __ldg(&x2[c * 32 + lane]);
        acc.x = fmaf(coef, zc.x, acc.x);
        acc.y = fmaf(coef, zc.y, acc.y);
    }
    ((float2*)g_T1)[r * 32 + lane] = acc;
}

// 4) fused: T2 = 2 L T1 - x (into smem) + out = x@W0 + T1@W1 + T2@W2 + bias
// 256 threads, 32 rows per block
__global__ void k_fused(const float* __restrict__ x,
                        const float* __restrict__ w,
                        const float* __restrict__ bias,
                        float* __restrict__ out) {
    __shared__ float ws[64 * 64];   // current W_m (16 KB)
    __shared__ float ts[32 * 64];   // row tile (8 KB)
    int tid  = threadIdx.x;
    int o    = tid & 63;
    int ty   = tid >> 6;            // 0..3
    int wid  = tid >> 5;            // 0..7
    int lane = tid & 31;
    int r0   = blockIdx.x * 32;

    // ---- phase 1: compute T2 rows r0..r0+31 into ts ----
    const float2* __restrict__ t1 = (const float2*)g_T1;
    const float2* __restrict__ x2 = (const float2*)x;
    #pragma unroll
    for (int q = 0; q < 4; q++) {
        int rl = wid * 4 + q;
        int r  = r0 + rl;
        float dr = g_deg[r];
        float diag = 1.0f - 1.0f / dr;

        float2 acc = __ldg(&t1[r * 32 + lane]);
        acc.x *= diag; acc.y *= diag;

        int nnz = g_cnt2[r];
        const float2* __restrict__ ell = g_ell + r * ELLW;
        #pragma unroll 8
        for (int k = 0; k < nnz; k++) {
            float2 e = __ldg(&ell[k]);
            int c = __float_as_int(e.x);
            float2 zc = __ldg(&t1[c * 32 + lane]);
            acc.x = fmaf(e.y, zc.x, acc.x);
            acc.y = fmaf(e.y, zc.y, acc.y);
        }
        float2 x0 = __ldg(&x2[r * 32 + lane]);
        acc.x = 2.0f * acc.x - x0.x;
        acc.y = 2.0f * acc.y - x0.y;
        ((float2*)(ts + rl * 64))[lane] = acc;
    }
    // stage W2 while ts holds T2
    for (int idx = tid; idx < 4096; idx += 256) ws[idx] = w[2 * 4096 + idx];
    __syncthreads();

    // ---- phase 2: GEMM over m = {2 (ts), 0 (x), 1 (T1)} ----
    float b = __ldg(&bias[o]);
    float acc[8];
    #pragma unroll
    for (int q = 0; q < 8; q++) acc[q] = b;

    const float* gsrc[2];
    gsrc[0] = x    + r0 * 64;   // m=0
    gsrc[1] = g_T1 + r0 * 64;   // m=1

    for (int phase = 0; phase < 3; phase++) {
        if (phase > 0) {
            __syncthreads();   // previous compute done before overwriting ts/ws
            int m = phase - 1; // 0 then 1
            for (int idx = tid; idx < 4096; idx += 256) ws[idx] = w[m * 4096 + idx];
            const float4* src = (const float4*)gsrc[m];
            float4* dst = (float4*)ts;
            for (int idx = tid; idx < 32 * 16; idx += 256) dst[idx] = src[idx];
            __syncthreads();
        }
        #pragma unroll 2
        for (int i4 = 0; i4 < 16; i4++) {
            float w0 = ws[(i4 * 4 + 0) * 64 + o];
            float w1 = ws[(i4 * 4 + 1) * 64 + o];
            float w2 = ws[(i4 * 4 + 2) * 64 + o];
            float w3 = ws[(i4 * 4 + 3) * 64 + o];
            #pragma unroll
            for (int q = 0; q < 8; q++) {
                float4 tv = ((const float4*)(ts + (ty * 8 + q) * 64))[i4];
                acc[q] = fmaf(tv.x, w0, fmaf(tv.y, w1,
                         fmaf(tv.z, w2, fmaf(tv.w, w3, acc[q]))));
            }
        }
    }
    #pragma unroll
    for (int q = 0; q < 8; q++)
        out[(r0 + ty * 8 + q) * 64 + o] = acc[q];
}

extern "C" void kernel_launch(void* const* d_in, const int* in_sizes, int n_in,
                              void* d_out, int out_size) {
    const float* x    = (const float*)d_in[0];
    const void*  ei   = (const void*)d_in[1];
    const float* ew   = (const float*)d_in[2];
    const float* w    = (const float*)d_in[3];
    const float* aw   = (const float*)d_in[4];
    const float* bias = (const float*)d_in[5];
    float* out = (float*)d_out;

    k_setup  <<<1, 32>>>(ei, aw);
    k_scatter<<<EE / 256, 256>>>(ei);
    k_dedup  <<<NN / 8, 256>>>(ew);
    k_spmm1  <<<NN * 32 / 256, 256>>>(x);
    k_fused  <<<NN / 32, 256>>>(x, w, bias, out);
}

// round 7
// speedup vs baseline: 1.3780x; 1.3780x over previous
#include <cuda_runtime.h>
#include <math.h>

#define NN    8192
#define EE    262144
#define CC    64
#define ELLW  128   // Poisson(32) tail beyond 128 ~ 1e-40

// ---- scratch (__device__ globals; zeroed at module load) ----
__device__ int    g_cnt[NN];           // raw scatter counts (self-reset by dedup)
__device__ int    g_cnt2[NN];          // deduped counts
__device__ float  g_deg[NN];
__device__ float  g_sinv[NN];          // rsqrt(deg)
__device__ int2   g_ellcj[NN * ELLW];  // raw: (col, edge id)
__device__ float2 g_ell[NN * ELLW];    // winners: (col_as_float, w -> coef)
__device__ float  g_T1[NN * CC];
__device__ float  g_T2[NN * CC];
__device__ float  g_gate;
__device__ int    g_is32;

__device__ __forceinline__ void load_rc(const void* ei, int j, int& r, int& c) {
    if (g_is32) {
        const int* e = (const int*)ei;
        r = e[j]; c = e[EE + j];
    } else {
        const long long* e = (const long long*)ei;
        r = (int)e[j]; c = (int)e[EE + j];
    }
}

// 0) dtype detect + gate (one warp)
__global__ void k_setup(const void* ei, const float* __restrict__ aw) {
    const long long* e64 = (const long long*)ei;
    int lane = threadIdx.x;
    long long v0 = e64[lane];
    long long v1 = e64[32 + lane];
    int bad = (v0 < 0 || v0 >= NN || v1 < 0 || v1 >= NN);
    unsigned any = __any_sync(0xffffffffu, bad);
    if (lane == 0) {
        g_is32 = any ? 1 : 0;
        g_gate = 1.0f / (1.0f + expf(-aw[0]));
    }
}

// 1) scatter edges into per-row lists (order nondeterministic; j recorded)
__global__ void k_scatter(const void* __restrict__ ei) {
    int j = blockIdx.x * blockDim.x + threadIdx.x;
    if (j >= EE) return;
    int r, c; load_rc(ei, j, r, c);
    int pos = atomicAdd(&g_cnt[r], 1);
    if (pos < ELLW) g_ellcj[r * ELLW + pos] = make_int2(c, j);
}

// 2) per-row dedupe via 256-slot per-warp shared hash.
//    entry = (col+1)<<18 | j  -> atomicMax = last-write-wins on edge id.
//    Self-resets g_cnt[r] for the next graph replay.
__global__ void k_dedup(const float* __restrict__ ew) {
    __shared__ unsigned tab[8][256];
    int wid  = threadIdx.x >> 5;
    int lane = threadIdx.x & 31;
    #pragma unroll
    for (int i = 0; i < 8; i++) tab[wid][lane + 32 * i] = 0u;
    __syncwarp();

    int r = blockIdx.x * 8 + wid;
    int nnz = min(g_cnt[r], ELLW);

    for (int k = lane; k < nnz; k += 32) {
        int2 cj = g_ellcj[r * ELLW + k];
        unsigned c = (unsigned)cj.x;
        unsigned entry = ((c + 1u) << 18) | (unsigned)cj.y;
        unsigned h = (c * 2654435761u) >> 24;
        for (;;) {
            unsigned cur = tab[wid][h];
            if (cur == 0u) {
                unsigned old = atomicCAS(&tab[wid][h], 0u, entry);
                if (old == 0u) break;
                cur = old;
            }
            if ((cur >> 18) == c + 1u) { atomicMax(&tab[wid][h], entry); break; }
            h = (h + 1u) & 255u;
        }
    }
    __syncwarp();

    float gate = g_gate;
    float degsum = 0.0f;
    int outpos = 0;
    #pragma unroll
    for (int it = 0; it < 8; it++) {
        unsigned e = tab[wid][lane + 32 * it];
        bool alive = (e != 0u);
        int c = 0; float wv = 0.0f;
        if (alive) {
            c = (int)(e >> 18) - 1;
            int j = (int)(e & 0x3FFFFu);
            wv = __ldg(&ew[j]) * gate;
            degsum += wv;
        }
        unsigned bal = __ballot_sync(0xffffffffu, alive);
        int pos = outpos + __popc(bal & ((1u << lane) - 1u));
        if (alive) g_ell[r * ELLW + pos] = make_float2(__int_as_float(c), wv);
        outpos += __popc(bal);
    }
    #pragma unroll
    for (int off = 16; off > 0; off >>= 1)
        degsum += __shfl_xor_sync(0xffffffffu, degsum, off);
    if (lane == 0) {
        float d = 1.0f + degsum;
        g_cnt2[r] = outpos;
        g_deg[r]  = d;
        g_sinv[r] = rsqrtf(d);
        g_cnt[r]  = 0;              // reset for next replay
    }
}

// 3) T1 = L x. Pre-pass: finalize coefs (registers + writeback for spmm2),
//    then main loop broadcasts (col, coef) via shfl — only mem op is the gather.
__global__ void k_spmm1(const float* __restrict__ x) {
    int gtid = blockIdx.x * blockDim.x + threadIdx.x;
    int r = gtid >> 5;
    int lane = gtid & 31;

    const float2* __restrict__ x2 = (const float2*)x;
    float dr = g_deg[r];
    float sr = g_sinv[r];
    float diag = 1.0f - 1.0f / dr;

    int nnz = g_cnt2[r];
    float2* __restrict__ ell = g_ell + r * ELLW;

    // pre-pass: lane owns entries lane, lane+32, lane+64, lane+96
    int   mycol[4];
    float mycoef[4];
    #pragma unroll
    for (int b = 0; b < 4; b++) {
        int k = b * 32 + lane;
        if (k < nnz) {
            float2 e = ell[k];
            int c = __float_as_int(e.x);
            float coef = -sr * e.y * __ldg(&g_sinv[c]);
            mycol[b]  = c;
            mycoef[b] = coef;
            ell[k].y  = coef;       // final coef for spmm2
        }
    }
    __syncwarp();

    float2 acc = __ldg(&x2[r * 32 + lane]);
    acc.x *= diag; acc.y *= diag;

    #pragma unroll
    for (int b = 0; b < 4; b++) {
        int cnt = nnz - b * 32;
        if (cnt <= 0) break;
        if (cnt > 32) cnt = 32;
        #pragma unroll 8
        for (int l = 0; l < cnt; l++) {
            int   c    = __shfl_sync(0xffffffffu, mycol[b],  l);
            float coef = __shfl_sync(0xffffffffu, mycoef[b], l);
            float2 zc = __ldg(&x2[c * 32 + lane]);
            acc.x = fmaf(coef, zc.x, acc.x);
            acc.y = fmaf(coef, zc.y, acc.y);
        }
    }
    ((float2*)g_T1)[r * 32 + lane] = acc;
}

// 4) T2 = 2 L T1 - x  (coefficients already final)
__global__ void k_spmm2(const float* __restrict__ x) {
    int gtid = blockIdx.x * blockDim.x + threadIdx.x;
    int r = gtid >> 5;
    int lane = gtid & 31;

    const float2* __restrict__ t1 = (const float2*)g_T1;
    float dr = g_deg[r];
    float diag = 1.0f - 1.0f / dr;

    float2 acc = __ldg(&t1[r * 32 + lane]);
    acc.x *= diag; acc.y *= diag;

    int nnz = g_cnt2[r];
    const float2* __restrict__ ell = g_ell + r * ELLW;
    #pragma unroll 8
    for (int k = 0; k < nnz; k++) {
        float2 e = __ldg(&ell[k]);
        int c = __float_as_int(e.x);
        float2 zc = __ldg(&t1[c * 32 + lane]);
        acc.x = fmaf(e.y, zc.x, acc.x);
        acc.y = fmaf(e.y, zc.y, acc.y);
    }
    float2 x0 = __ldg(&((const float2*)x)[r * 32 + lane]);
    acc.x = 2.0f * acc.x - x0.x;
    acc.y = 2.0f * acc.y - x0.y;
    ((float2*)g_T2)[r * 32 + lane] = acc;
}

// 5) fused output GEMM: out = x@W0 + T1@W1 + T2@W2 + bias
__global__ void k_out(const float* __restrict__ x,
                      const float* __restrict__ w,
                      const float* __restrict__ bias,
                      float* __restrict__ out) {
    __shared__ float ws[64 * 64];   // current W_m (16 KB)
    __shared__ float ts[32 * 64];   // 32-row tile of T_m (8 KB)
    int tid = threadIdx.x;
    int o  = tid & 63;
    int ty = tid >> 6;              // 0..3
    int r0 = blockIdx.x * 32;

    float b = __ldg(&bias[o]);
    float acc[8];
    #pragma unroll
    for (int q = 0; q < 8; q++) acc[q] = b;

    const float* mats[3];
    mats[0] = x    + r0 * 64;
    mats[1] = g_T1 + r0 * 64;
    mats[2] = g_T2 + r0 * 64;

    for (int m = 0; m < 3; m++) {
        for (int idx = tid; idx < 4096; idx += 256) ws[idx] = w[m * 4096 + idx];
        const float4* src = (const float4*)mats[m];
        float4* dst = (float4*)ts;
        for (int idx = tid; idx < 32 * 16; idx += 256) dst[idx] = src[idx];
        __syncthreads();

        #pragma unroll 2
        for (int i4 = 0; i4 < 16; i4++) {
            float w0 = ws[(i4 * 4 + 0) * 64 + o];
            float w1 = ws[(i4 * 4 + 1) * 64 + o];
            float w2 = ws[(i4 * 4 + 2) * 64 + o];
            float w3 = ws[(i4 * 4 + 3) * 64 + o];
            #pragma unroll
            for (int q = 0; q < 8; q++) {
                float4 tv = ((const float4*)(ts + (ty * 8 + q) * 64))[i4];
                acc[q] = fmaf(tv.x, w0, fmaf(tv.y, w1,
                         fmaf(tv.z, w2, fmaf(tv.w, w3, acc[q]))));
            }
        }
        __syncthreads();
    }
    #pragma unroll
    for (int q = 0; q < 8; q++)
        out[(r0 + ty * 8 + q) * 64 + o] = acc[q];
}

extern "C" void kernel_launch(void* const* d_in, const int* in_sizes, int n_in,
                              void* d_out, int out_size) {
    const float* x    = (const float*)d_in[0];
    const void*  ei   = (const void*)d_in[1];
    const float* ew   = (const float*)d_in[2];
    const float* w    = (const float*)d_in[3];
    const float* aw   = (const float*)d_in[4];
    const float* bias = (const float*)d_in[5];
    float* out = (float*)d_out;

    k_setup  <<<1, 32>>>(ei, aw);
    k_scatter<<<EE / 256, 256>>>(ei);
    k_dedup  <<<NN / 8, 256>>>(ew);
    k_spmm1  <<<NN * 32 / 256, 256>>>(x);
    k_spmm2  <<<NN * 32 / 256, 256>>>(x);
    k_out    <<<NN / 32, 256>>>(x, w, bias, out);
}